// round 4
// baseline (speedup 1.0000x reference)
#include <cuda_runtime.h>
#include <cstdint>

#define DEVI static __device__ __forceinline__

namespace {
constexpr int B_ = 256;   // batch
constexpr int T_ = 256;   // time
constexpr int D_ = 64;    // input dim
constexpr int H_ = 512;   // hidden
constexpr int FOURH = 4 * H_;          // 2048
constexpr int M_ALL = B_ * T_;         // 65536
}

// ---------- scratch (device globals; NO allocations anywhere) ----------
__device__ float g_xw[(size_t)M_ALL * FOURH];  // 512 MB: per-(b,t) input projections [b*T+t][4H]
__device__ float g_h1[(size_t)M_ALL * H_];     // 128 MB: layer-0 hidden sequence [b*T+t][H]
__device__ float g_hbuf[2][B_ * H_];           // ping-pong hidden state
__device__ float g_c[B_ * H_];                 // cell state
__device__ float g_sum[B_ * H_];               // sum over t of layer-1 h
__device__ float g_head[B_ * 256];             // shared-head output

// ---------- helpers ----------
DEVI float tf32r(float x) {
    unsigned u;
    asm("cvt.rna.tf32.f32 %0, %1;" : "=r"(u) : "f"(x));
    return __uint_as_float(u);
}

DEVI void mma8(float* c, const unsigned* a, unsigned b0, unsigned b1) {
    asm volatile(
        "mma.sync.aligned.m16n8k8.row.col.f32.tf32.tf32.f32 "
        "{%0,%1,%2,%3}, {%4,%5,%6,%7}, {%8,%9}, {%0,%1,%2,%3};\n"
        : "+f"(c[0]), "+f"(c[1]), "+f"(c[2]), "+f"(c[3])
        : "r"(a[0]), "r"(a[1]), "r"(a[2]), "r"(a[3]), "r"(b0), "r"(b1));
}

DEVI float sigmoidf_(float x) { return 1.0f / (1.0f + __expf(-x)); }

DEVI float tanhf_(float x) {
    x = fminf(fmaxf(x, -15.0f), 15.0f);
    float e = __expf(-2.0f * x);
    return (1.0f - e) / (1.0f + e);
}

// ---------- zero state (run at start and between layers; deterministic per call) ----------
__global__ void zero_state_kernel() {
    int i = blockIdx.x * blockDim.x + threadIdx.x;
    if (i < B_ * H_) {
        g_hbuf[0][i] = 0.0f;
        g_hbuf[1][i] = 0.0f;
        g_c[i] = 0.0f;
        g_sum[i] = 0.0f;   // still zero at mid-call; re-zeroing is harmless
    }
}

// ---------- big input-projection GEMM: g_xw[M_ALL][4H] = A[M_ALL][K] @ W[4H][K]^T + bias ----------
// Block tile 64x64, 128 threads (4 warps in 2x2, each warp 32x32), tf32 mma, K chunk 32.
__global__ void __launch_bounds__(128) gemm_xw_kernel(
    const float* __restrict__ Aext, int useH1,
    const float* __restrict__ W, const float* __restrict__ bias, int K)
{
    __shared__ float As[64][33];
    __shared__ float Bs[64][33];
    const float* __restrict__ A = useH1 ? g_h1 : Aext;

    const int tid = threadIdx.x;
    const int lane = tid & 31;
    const int w = tid >> 5;
    const int wm = w >> 1, wn = w & 1;
    const int grp = lane >> 2, tig = lane & 3;
    const int m0 = blockIdx.x * 64;
    const int j0 = blockIdx.y * 64;

    float acc[2][4][4] = {};

    for (int kc = 0; kc < K; kc += 32) {
        __syncthreads();
        // load A tile 64x32 (512 float4, 4 per thread), rounding to tf32 at store
#pragma unroll
        for (int i = 0; i < 4; i++) {
            int q = tid + 128 * i;
            int r = q >> 3, c4 = (q & 7) * 4;
            float4 v = *reinterpret_cast<const float4*>(&A[(size_t)(m0 + r) * K + kc + c4]);
            As[r][c4 + 0] = tf32r(v.x);
            As[r][c4 + 1] = tf32r(v.y);
            As[r][c4 + 2] = tf32r(v.z);
            As[r][c4 + 3] = tf32r(v.w);
        }
        // load W tile 64x32 (rows are output cols j0..j0+63)
#pragma unroll
        for (int i = 0; i < 4; i++) {
            int q = tid + 128 * i;
            int r = q >> 3, c4 = (q & 7) * 4;
            float4 v = *reinterpret_cast<const float4*>(&W[(size_t)(j0 + r) * K + kc + c4]);
            Bs[r][c4 + 0] = tf32r(v.x);
            Bs[r][c4 + 1] = tf32r(v.y);
            Bs[r][c4 + 2] = tf32r(v.z);
            Bs[r][c4 + 3] = tf32r(v.w);
        }
        __syncthreads();

#pragma unroll
        for (int ks = 0; ks < 4; ks++) {
            unsigned a[2][4];
#pragma unroll
            for (int mt = 0; mt < 2; mt++) {
                int rb = wm * 32 + mt * 16;
                a[mt][0] = __float_as_uint(As[rb + grp][ks * 8 + tig]);
                a[mt][1] = __float_as_uint(As[rb + grp + 8][ks * 8 + tig]);
                a[mt][2] = __float_as_uint(As[rb + grp][ks * 8 + tig + 4]);
                a[mt][3] = __float_as_uint(As[rb + grp + 8][ks * 8 + tig + 4]);
            }
#pragma unroll
            for (int nt = 0; nt < 4; nt++) {
                int cb = wn * 32 + nt * 8;
                unsigned b0 = __float_as_uint(Bs[cb + grp][ks * 8 + tig]);
                unsigned b1 = __float_as_uint(Bs[cb + grp][ks * 8 + tig + 4]);
                mma8(acc[0][nt], a[0], b0, b1);
                mma8(acc[1][nt], a[1], b0, b1);
            }
        }
    }

    // epilogue: + bias, write g_xw
#pragma unroll
    for (int mt = 0; mt < 2; mt++) {
#pragma unroll
        for (int nt = 0; nt < 4; nt++) {
            int row = m0 + wm * 32 + mt * 16 + grp;
            int col = j0 + wn * 32 + nt * 8 + tig * 2;
            float bv0 = bias[col], bv1 = bias[col + 1];
            g_xw[(size_t)row * FOURH + col] = acc[mt][nt][0] + bv0;
            g_xw[(size_t)row * FOURH + col + 1] = acc[mt][nt][1] + bv1;
            g_xw[(size_t)(row + 8) * FOURH + col] = acc[mt][nt][2] + bv0;
            g_xw[(size_t)(row + 8) * FOURH + col + 1] = acc[mt][nt][3] + bv1;
        }
    }
}

// ---------- one LSTM timestep ----------
// Grid (B/32, H/32), 128 threads. Block computes gates for a 32x32 (batch x hidden) tile:
// warp w computes gate w's 32x32 via tf32 mma over K=H, then cross-warp exchange in smem
// and fused activation + cell update. mode 0: write h1 sequence; mode 1: accumulate sum.
__global__ void __launch_bounds__(128) lstm_step_kernel(
    const float* __restrict__ Whh, int t, int mode)
{
    __shared__ float As[32][33];
    __shared__ float Bs[4][32][33];   // per-gate weight chunk; reused as gate-output tile

    const int tid = threadIdx.x;
    const int lane = tid & 31;
    const int w = tid >> 5;
    const int grp = lane >> 2, tig = lane & 3;
    const int m0 = blockIdx.x * 32;
    const int j0 = blockIdx.y * 32;

    const float* __restrict__ hprev = g_hbuf[t & 1];
    float* __restrict__ hnext = g_hbuf[(t + 1) & 1];

    float acc[2][4][4] = {};

    for (int kc = 0; kc < H_; kc += 32) {
        __syncthreads();
        // A tile: hprev[m0..m0+31][kc..kc+31] (256 float4, 2 per thread)
#pragma unroll
        for (int i = 0; i < 2; i++) {
            int q = tid + 128 * i;
            int r = q >> 3, c4 = (q & 7) * 4;
            float4 v = *reinterpret_cast<const float4*>(&hprev[(m0 + r) * H_ + kc + c4]);
            As[r][c4 + 0] = tf32r(v.x);
            As[r][c4 + 1] = tf32r(v.y);
            As[r][c4 + 2] = tf32r(v.z);
            As[r][c4 + 3] = tf32r(v.w);
        }
        // B tiles: 4 gates x Whh[g*H + j0 + r][kc..] (1024 float4, 8 per thread)
#pragma unroll
        for (int i = 0; i < 8; i++) {
            int q = tid + 128 * i;
            int g2 = q >> 8, r = (q >> 3) & 31, c4 = (q & 7) * 4;
            float4 v = *reinterpret_cast<const float4*>(
                &Whh[(size_t)(g2 * H_ + j0 + r) * H_ + kc + c4]);
            Bs[g2][r][c4 + 0] = tf32r(v.x);
            Bs[g2][r][c4 + 1] = tf32r(v.y);
            Bs[g2][r][c4 + 2] = tf32r(v.z);
            Bs[g2][r][c4 + 3] = tf32r(v.w);
        }
        __syncthreads();

#pragma unroll
        for (int ks = 0; ks < 4; ks++) {
            unsigned a[2][4];
#pragma unroll
            for (int mt = 0; mt < 2; mt++) {
                int rb = mt * 16;
                a[mt][0] = __float_as_uint(As[rb + grp][ks * 8 + tig]);
                a[mt][1] = __float_as_uint(As[rb + grp + 8][ks * 8 + tig]);
                a[mt][2] = __float_as_uint(As[rb + grp][ks * 8 + tig + 4]);
                a[mt][3] = __float_as_uint(As[rb + grp + 8][ks * 8 + tig + 4]);
            }
#pragma unroll
            for (int nt = 0; nt < 4; nt++) {
                int cb = nt * 8;
                unsigned b0 = __float_as_uint(Bs[w][cb + grp][ks * 8 + tig]);
                unsigned b1 = __float_as_uint(Bs[w][cb + grp][ks * 8 + tig + 4]);
                mma8(acc[0][nt], a[0], b0, b1);
                mma8(acc[1][nt], a[1], b0, b1);
            }
        }
    }

    // each warp writes its own gate tile into its own Bs[w] region (no cross-warp hazard)
#pragma unroll
    for (int mt = 0; mt < 2; mt++) {
#pragma unroll
        for (int nt = 0; nt < 4; nt++) {
            int r = mt * 16 + grp, c = nt * 8 + tig * 2;
            Bs[w][r][c] = acc[mt][nt][0];
            Bs[w][r][c + 1] = acc[mt][nt][1];
            Bs[w][r + 8][c] = acc[mt][nt][2];
            Bs[w][r + 8][c + 1] = acc[mt][nt][3];
        }
    }
    __syncthreads();

    // fused activation + cell update: 1024 elems, 8 per thread
#pragma unroll
    for (int i = 0; i < 8; i++) {
        int e = tid + 128 * i;
        int r = e >> 5, c = e & 31;
        int b = m0 + r, hc = j0 + c;
        const float* xwr = &g_xw[((size_t)b * T_ + t) * FOURH];
        float gi = Bs[0][r][c] + xwr[hc];
        float gf = Bs[1][r][c] + xwr[H_ + hc];
        float gg = Bs[2][r][c] + xwr[2 * H_ + hc];
        float go = Bs[3][r][c] + xwr[3 * H_ + hc];
        float ii = sigmoidf_(gi);
        float ff = sigmoidf_(gf);
        float gt = tanhf_(gg);
        float oo = sigmoidf_(go);
        float cc = ff * g_c[b * H_ + hc] + ii * gt;
        g_c[b * H_ + hc] = cc;
        float hh = oo * tanhf_(cc);
        hnext[b * H_ + hc] = hh;
        if (mode == 0) {
            g_h1[((size_t)b * T_ + t) * H_ + hc] = hh;
        } else {
            g_sum[b * H_ + hc] += hh;
        }
    }
}

// ---------- heads ----------
__global__ void __launch_bounds__(256) head1_kernel(
    const float* __restrict__ Wsh, const float* __restrict__ bsh)
{
    __shared__ float last[H_];
    const int b = blockIdx.x, j = threadIdx.x;
    for (int k = j; k < H_; k += 256) last[k] = g_sum[b * H_ + k] * (1.0f / (float)T_);
    __syncthreads();
    const float4* wr = reinterpret_cast<const float4*>(Wsh + (size_t)j * H_);
    const float4* lr = reinterpret_cast<const float4*>(last);
    float s = bsh[j];
#pragma unroll 4
    for (int k = 0; k < H_ / 4; k++) {
        float4 wv = wr[k], lv = lr[k];
        s += wv.x * lv.x + wv.y * lv.y + wv.z * lv.z + wv.w * lv.w;
    }
    g_head[b * 256 + j] = fmaxf(s, 0.0f) * 1.5f;
}

__global__ void __launch_bounds__(256) head2_kernel(
    const float* __restrict__ Wd, const float* __restrict__ bd,
    const float* __restrict__ Wm, const float* __restrict__ bm,
    float* __restrict__ out)
{
    const int b = threadIdx.x;
    const float4* hr = reinterpret_cast<const float4*>(g_head + b * 256);
    const float4* wd4 = reinterpret_cast<const float4*>(Wd);
    const float4* wm4 = reinterpret_cast<const float4*>(Wm);
    float sd = 0.0f, sm = 0.0f;
#pragma unroll 8
    for (int k = 0; k < 64; k++) {
        float4 h = hr[k], a = wd4[k], m = wm4[k];
        sd += h.x * a.x + h.y * a.y + h.z * a.z + h.w * a.w;
        sm += h.x * m.x + h.y * m.y + h.z * m.z + h.w * m.w;
    }
    out[b] = sd + bd[0];
    out[256 + b] = sm + bm[0];
}

// ---------- launch ----------
extern "C" void kernel_launch(void* const* d_in, const int* in_sizes, int n_in,
                              void* d_out, int out_size)
{
    (void)in_sizes; (void)n_in; (void)out_size;
    const float* x    = (const float*)d_in[0];
    const float* Wih0 = (const float*)d_in[1];
    const float* Whh0 = (const float*)d_in[2];
    const float* b0   = (const float*)d_in[3];
    const float* Wih1 = (const float*)d_in[4];
    const float* Whh1 = (const float*)d_in[5];
    const float* b1   = (const float*)d_in[6];
    const float* Wsh  = (const float*)d_in[7];
    const float* bsh  = (const float*)d_in[8];
    const float* Wdir = (const float*)d_in[9];
    const float* bdir = (const float*)d_in[10];
    const float* Wmag = (const float*)d_in[11];
    const float* bmag = (const float*)d_in[12];
    float* out = (float*)d_out;

    const dim3 gGemm(M_ALL / 64, FOURH / 64);   // (1024, 32)
    const dim3 gStep(B_ / 32, H_ / 32);         // (8, 16)
    const int zBlocks = (B_ * H_ + 255) / 256;

    // layer 0
    zero_state_kernel<<<zBlocks, 256>>>();
    gemm_xw_kernel<<<gGemm, 128>>>(x, 0, Wih0, b0, D_);
    for (int t = 0; t < T_; t++)
        lstm_step_kernel<<<gStep, 128>>>(Whh0, t, 0);

    // layer 1
    zero_state_kernel<<<zBlocks, 256>>>();
    gemm_xw_kernel<<<gGemm, 128>>>(nullptr, 1, Wih1, b1, H_);
    for (int t = 0; t < T_; t++)
        lstm_step_kernel<<<gStep, 128>>>(Whh1, t, 1);

    // heads
    head1_kernel<<<B_, 256>>>(Wsh, bsh);
    head2_kernel<<<1, 256>>>(Wdir, bdir, Wmag, bmag, out);
}

// round 11
// speedup vs baseline: 2.5514x; 2.5514x over previous
#include <cuda_runtime.h>
#include <cstdint>

#define DEVI static __device__ __forceinline__

namespace {
constexpr int B_ = 256;   // batch
constexpr int T_ = 256;   // time
constexpr int D_ = 64;    // input dim
constexpr int H_ = 512;   // hidden
constexpr int FOURH = 4 * H_;          // 2048
constexpr int M_ALL = B_ * T_;         // 65536

// step-kernel tiling: 4 batch-groups x 64 rows, 32 j-tiles x 16 cols
constexpr int NBG = 4;
constexpr int NJT = 32;
constexpr int MB = 64;                 // batch rows per block
constexpr int WJ = 16;                 // hidden cols per block (per gate)
constexpr int GRID_S = NBG * NJT;      // 128 blocks

constexpr int G_STRIDE = 17;
}

// ---------- scratch (device globals; NO allocations anywhere) ----------
__device__ float g_xw[(size_t)M_ALL * FOURH];  // input projections, layout [t][B][4H]
__device__ float g_h1[(size_t)M_ALL * H_];     // layer-0 hidden sequence [b][t][H]
__device__ float g_hbuf[2][B_ * H_];           // ping-pong hidden state
__device__ float g_c[B_ * H_];                 // cell state
__device__ float g_sum[B_ * H_];               // sum over t of layer-1 h
__device__ float g_head[B_ * 256];             // shared-head output

// ---------- helpers ----------
DEVI float tf32r(float x) {
    unsigned u;
    asm("cvt.rna.tf32.f32 %0, %1;" : "=r"(u) : "f"(x));
    return __uint_as_float(u);
}

DEVI void mma8(float* c, const unsigned* a, unsigned b0, unsigned b1) {
    asm volatile(
        "mma.sync.aligned.m16n8k8.row.col.f32.tf32.tf32.f32 "
        "{%0,%1,%2,%3}, {%4,%5,%6,%7}, {%8,%9}, {%0,%1,%2,%3};\n"
        : "+f"(c[0]), "+f"(c[1]), "+f"(c[2]), "+f"(c[3])
        : "r"(a[0]), "r"(a[1]), "r"(a[2]), "r"(a[3]), "r"(b0), "r"(b1));
}

DEVI void cpasync16(void* dst_smem, const void* src) {
    unsigned d = (unsigned)__cvta_generic_to_shared(dst_smem);
    asm volatile("cp.async.cg.shared.global [%0], [%1], 16;\n" :: "r"(d), "l"(src));
}
DEVI void cpcommit() { asm volatile("cp.async.commit_group;\n" ::: "memory"); }
DEVI void cpwait1() { asm volatile("cp.async.wait_group 1;\n" ::: "memory"); }
DEVI void cpwait0() { asm volatile("cp.async.wait_group 0;\n" ::: "memory"); }

DEVI float sigmoidf_(float x) { return 1.0f / (1.0f + __expf(-x)); }

DEVI float tanhf_(float x) {
    x = fminf(fmaxf(x, -15.0f), 15.0f);
    float e = __expf(-2.0f * x);
    return (1.0f - e) / (1.0f + e);
}

// ---------- zero state ----------
__global__ void zero_state_kernel() {
    int i = blockIdx.x * blockDim.x + threadIdx.x;
    if (i < B_ * H_) {
        g_hbuf[0][i] = 0.0f;
        g_c[i] = 0.0f;
        g_sum[i] = 0.0f;
    }
}

// ---------- big input-projection GEMM ----------
// out[t][B][4H] = A[M][K] @ W[4H][K]^T + bias  (A rows m = b*T+t)
// Block tile 128x64, 256 threads (8 warps, 4x2 of 32x32), tf32 mma, K chunk 32.
__global__ void __launch_bounds__(256) gemm_xw_kernel(
    const float* __restrict__ Aext, int useH1,
    const float* __restrict__ W, const float* __restrict__ bias, int K)
{
    __shared__ float As[128][36];
    __shared__ float Bs[64][36];
    const float* __restrict__ A = useH1 ? g_h1 : Aext;

    const int tid = threadIdx.x;
    const int lane = tid & 31;
    const int w = tid >> 5;
    const int wm = w >> 1, wn = w & 1;
    const int grp = lane >> 2, tig = lane & 3;
    const int m0 = blockIdx.x * 128;
    const int j0 = blockIdx.y * 64;

    float acc[2][4][4] = {};

    for (int kc = 0; kc < K; kc += 32) {
        __syncthreads();
#pragma unroll
        for (int i = 0; i < 4; i++) {               // A tile 128x32
            int q = tid + 256 * i;
            int r = q >> 3, c4 = (q & 7) << 2;
            float4 v = *reinterpret_cast<const float4*>(&A[(size_t)(m0 + r) * K + kc + c4]);
            As[r][c4 + 0] = tf32r(v.x);
            As[r][c4 + 1] = tf32r(v.y);
            As[r][c4 + 2] = tf32r(v.z);
            As[r][c4 + 3] = tf32r(v.w);
        }
#pragma unroll
        for (int i = 0; i < 2; i++) {               // W tile 64x32
            int q = tid + 256 * i;
            int r = q >> 3, c4 = (q & 7) << 2;
            float4 v = *reinterpret_cast<const float4*>(&W[(size_t)(j0 + r) * K + kc + c4]);
            Bs[r][c4 + 0] = tf32r(v.x);
            Bs[r][c4 + 1] = tf32r(v.y);
            Bs[r][c4 + 2] = tf32r(v.z);
            Bs[r][c4 + 3] = tf32r(v.w);
        }
        __syncthreads();

#pragma unroll
        for (int ks = 0; ks < 4; ks++) {
            unsigned a[2][4];
#pragma unroll
            for (int mt = 0; mt < 2; mt++) {
                int rb = wm * 32 + mt * 16;
                a[mt][0] = __float_as_uint(As[rb + grp][ks * 8 + tig]);
                a[mt][1] = __float_as_uint(As[rb + grp + 8][ks * 8 + tig]);
                a[mt][2] = __float_as_uint(As[rb + grp][ks * 8 + tig + 4]);
                a[mt][3] = __float_as_uint(As[rb + grp + 8][ks * 8 + tig + 4]);
            }
#pragma unroll
            for (int nt = 0; nt < 4; nt++) {
                int cb = wn * 32 + nt * 8;
                unsigned b0 = __float_as_uint(Bs[cb + grp][ks * 8 + tig]);
                unsigned b1 = __float_as_uint(Bs[cb + grp][ks * 8 + tig + 4]);
                mma8(acc[0][nt], a[0], b0, b1);
                mma8(acc[1][nt], a[1], b0, b1);
            }
        }
    }

    // epilogue: + bias, permuted write to [t][B][4H]
#pragma unroll
    for (int mt = 0; mt < 2; mt++) {
#pragma unroll
        for (int nt = 0; nt < 4; nt++) {
            int row = m0 + wm * 32 + mt * 16 + grp;
            int col = j0 + wn * 32 + nt * 8 + tig * 2;
            float bv0 = bias[col], bv1 = bias[col + 1];
#pragma unroll
            for (int half = 0; half < 2; half++) {
                int r = row + half * 8;
                int t = r & (T_ - 1), b = r >> 8;
                size_t o = ((size_t)t * B_ + b) * FOURH + col;
                g_xw[o] = acc[mt][nt][half * 2 + 0] + bv0;
                g_xw[o + 1] = acc[mt][nt][half * 2 + 1] + bv1;
            }
        }
    }
}

// ---------- one LSTM timestep (cp.async 2-stage pipelined, no inter-block sync) ----------
// Grid 128 blocks: bg = bid>>5 (64 batch rows), jt = bid&31 (16 hidden cols, all 4 gates).
// 256 threads / 8 warps: warp w -> gate (w&3), batch half (w>>2).
// Weight+A chunks (K=32) stream through a 2-stage cp.async pipeline. tf32 mma on raw
// fp32 bits (HW reads bits[31:13] -> RZ rounding; plenty of margin vs 1e-3).
__global__ void __launch_bounds__(256) lstm_step_kernel(
    const float* __restrict__ Whh, int t, int mode)  // mode 0: write g_h1; 1: accumulate sum
{
    __shared__ __align__(16) float SA[2][MB][36];  // h_prev stages (aliased as gate-exchange)
    __shared__ __align__(16) float SW[2][MB][36];  // weight stages (64 rows = 4 gates x 16 cols)

    const int tid = threadIdx.x;
    const int lane = tid & 31;
    const int w = tid >> 5;
    const int grp = lane >> 2, tig = lane & 3;
    const int bg = blockIdx.x >> 5;
    const int jt = blockIdx.x & 31;
    const int m0 = bg * MB;
    const int j0 = jt * WJ;
    const int g = w & 3;
    const int mb = (w >> 2) * 32;

    const float* __restrict__ hprev = g_hbuf[t & 1];
    float* __restrict__ hnext = g_hbuf[(t + 1) & 1];

    // chunk loader: stage s in {0,1}, K offset kc. 4 cp.async per thread (A: 2, W: 2).
    auto load_chunk = [&](int s, int kc) {
#pragma unroll
        for (int i = 0; i < 2; i++) {
            int p = tid + 256 * i;
            int row = p >> 3, seg = (p & 7) << 2;
            cpasync16(&SA[s][row][seg], &hprev[(m0 + row) * H_ + kc + seg]);
        }
#pragma unroll
        for (int i = 0; i < 2; i++) {
            int p = tid + 256 * i;
            int rw = p >> 3, seg = (p & 7) << 2;
            int g2 = rw >> 4, n = rw & 15;
            cpasync16(&SW[s][rw][seg],
                      &Whh[(size_t)(g2 * H_ + j0 + n) * H_ + kc + seg]);
        }
    };

    load_chunk(0, 0); cpcommit();
    load_chunk(1, 32); cpcommit();

    float acc[2][2][4] = {};

    for (int ci = 0; ci < 16; ci++) {
        const int s = ci & 1;
        cpwait1();          // chunk ci landed (one younger group may stay in flight)
        __syncthreads();

        const float* Ab = &SA[s][0][0];
        const float* Wb = &SW[s][g * WJ][0];
#pragma unroll
        for (int ks = 0; ks < 4; ks++) {
            unsigned a[2][4];
#pragma unroll
            for (int mt = 0; mt < 2; mt++) {
                int rb = mb + mt * 16;
                a[mt][0] = __float_as_uint(Ab[(rb + grp) * 36 + ks * 8 + tig]);
                a[mt][1] = __float_as_uint(Ab[(rb + grp + 8) * 36 + ks * 8 + tig]);
                a[mt][2] = __float_as_uint(Ab[(rb + grp) * 36 + ks * 8 + tig + 4]);
                a[mt][3] = __float_as_uint(Ab[(rb + grp + 8) * 36 + ks * 8 + tig + 4]);
            }
#pragma unroll
            for (int nt = 0; nt < 2; nt++) {
                unsigned b0 = __float_as_uint(Wb[(nt * 8 + grp) * 36 + ks * 8 + tig]);
                unsigned b1 = __float_as_uint(Wb[(nt * 8 + grp) * 36 + ks * 8 + tig + 4]);
                mma8(acc[0][nt], a[0], b0, b1);
                mma8(acc[1][nt], a[1], b0, b1);
            }
        }
        __syncthreads();    // all warps done reading stage s before refill / G-alias write

        if (ci + 2 < 16) { load_chunk(s, (ci + 2) * 32); }  // stage index s, NOT ci+2
        cpcommit();         // empty groups at the tail keep wait-group arithmetic uniform
    }
    cpwait0();              // drain (tail groups are empty)

    // gate exchange: Gsm aliases SA stages (4352 floats <= 4608 available)
    float* const Gsm = &SA[0][0][0];
#pragma unroll
    for (int mt = 0; mt < 2; mt++) {
#pragma unroll
        for (int nt = 0; nt < 2; nt++) {
            int r0 = mb + mt * 16 + grp;
            int c = nt * 8 + tig * 2;
            Gsm[(g * MB + r0) * G_STRIDE + c] = acc[mt][nt][0];
            Gsm[(g * MB + r0) * G_STRIDE + c + 1] = acc[mt][nt][1];
            Gsm[(g * MB + r0 + 8) * G_STRIDE + c] = acc[mt][nt][2];
            Gsm[(g * MB + r0 + 8) * G_STRIDE + c + 1] = acc[mt][nt][3];
        }
    }
    __syncthreads();

    // fused activation + cell update: 4 cells per thread
    const int b_loc = tid >> 2;
    const int hc0 = (tid & 3) * 4;
    const int b = m0 + b_loc;
    const size_t xo = ((size_t)t * B_ + b) * FOURH + j0 + hc0;
    const float4 xi = __ldg(reinterpret_cast<const float4*>(&g_xw[xo]));
    const float4 xf = __ldg(reinterpret_cast<const float4*>(&g_xw[xo + H_]));
    const float4 xg = __ldg(reinterpret_cast<const float4*>(&g_xw[xo + 2 * H_]));
    const float4 xo4 = __ldg(reinterpret_cast<const float4*>(&g_xw[xo + 3 * H_]));
    float4 c4 = *reinterpret_cast<float4*>(&g_c[b * H_ + j0 + hc0]);

    float gi[4] = {xi.x, xi.y, xi.z, xi.w};
    float gf[4] = {xf.x, xf.y, xf.z, xf.w};
    float gg[4] = {xg.x, xg.y, xg.z, xg.w};
    float go[4] = {xo4.x, xo4.y, xo4.z, xo4.w};
    float cr[4] = {c4.x, c4.y, c4.z, c4.w};
    float hv[4];
#pragma unroll
    for (int j = 0; j < 4; j++) {
        int gb = b_loc * G_STRIDE + hc0 + j;
        float ii = sigmoidf_(Gsm[gb] + gi[j]);
        float ff = sigmoidf_(Gsm[MB * G_STRIDE + gb] + gf[j]);
        float gt = tanhf_(Gsm[2 * MB * G_STRIDE + gb] + gg[j]);
        float oo = sigmoidf_(Gsm[3 * MB * G_STRIDE + gb] + go[j]);
        cr[j] = ff * cr[j] + ii * gt;
        hv[j] = oo * tanhf_(cr[j]);
    }
    *reinterpret_cast<float4*>(&g_c[b * H_ + j0 + hc0]) =
        make_float4(cr[0], cr[1], cr[2], cr[3]);
    float4 hv4 = make_float4(hv[0], hv[1], hv[2], hv[3]);
    *reinterpret_cast<float4*>(&hnext[b * H_ + j0 + hc0]) = hv4;
    if (mode == 0) {
        *reinterpret_cast<float4*>(&g_h1[((size_t)b * T_ + t) * H_ + j0 + hc0]) = hv4;
    } else {
        float4 s4 = *reinterpret_cast<float4*>(&g_sum[b * H_ + j0 + hc0]);
        s4.x += hv[0]; s4.y += hv[1]; s4.z += hv[2]; s4.w += hv[3];
        *reinterpret_cast<float4*>(&g_sum[b * H_ + j0 + hc0]) = s4;
    }
}

// ---------- heads ----------
__global__ void __launch_bounds__(256) head1_kernel(
    const float* __restrict__ Wsh, const float* __restrict__ bsh)
{
    __shared__ float last[H_];
    const int b = blockIdx.x, j = threadIdx.x;
    for (int k = j; k < H_; k += 256) last[k] = g_sum[b * H_ + k] * (1.0f / (float)T_);
    __syncthreads();
    const float4* wr = reinterpret_cast<const float4*>(Wsh + (size_t)j * H_);
    const float4* lr = reinterpret_cast<const float4*>(last);
    float s = bsh[j];
#pragma unroll 4
    for (int k = 0; k < H_ / 4; k++) {
        float4 wv = wr[k], lv = lr[k];
        s += wv.x * lv.x + wv.y * lv.y + wv.z * lv.z + wv.w * lv.w;
    }
    g_head[b * 256 + j] = fmaxf(s, 0.0f) * 1.5f;
}

__global__ void __launch_bounds__(256) head2_kernel(
    const float* __restrict__ Wd, const float* __restrict__ bd,
    const float* __restrict__ Wm, const float* __restrict__ bm,
    float* __restrict__ out)
{
    const int b = threadIdx.x;
    const float4* hr = reinterpret_cast<const float4*>(g_head + b * 256);
    const float4* wd4 = reinterpret_cast<const float4*>(Wd);
    const float4* wm4 = reinterpret_cast<const float4*>(Wm);
    float sd = 0.0f, smv = 0.0f;
#pragma unroll 8
    for (int k = 0; k < 64; k++) {
        float4 h = hr[k], a = wd4[k], m = wm4[k];
        sd += h.x * a.x + h.y * a.y + h.z * a.z + h.w * a.w;
        smv += h.x * m.x + h.y * m.y + h.z * m.z + h.w * m.w;
    }
    out[b] = sd + bd[0];
    out[256 + b] = smv + bm[0];
}

// ---------- launch ----------
extern "C" void kernel_launch(void* const* d_in, const int* in_sizes, int n_in,
                              void* d_out, int out_size)
{
    (void)in_sizes; (void)n_in; (void)out_size;
    const float* x    = (const float*)d_in[0];
    const float* Wih0 = (const float*)d_in[1];
    const float* Whh0 = (const float*)d_in[2];
    const float* b0   = (const float*)d_in[3];
    const float* Wih1 = (const float*)d_in[4];
    const float* Whh1 = (const float*)d_in[5];
    const float* b1   = (const float*)d_in[6];
    const float* Wsh  = (const float*)d_in[7];
    const float* bsh  = (const float*)d_in[8];
    const float* Wdir = (const float*)d_in[9];
    const float* bdir = (const float*)d_in[10];
    const float* Wmag = (const float*)d_in[11];
    const float* bmag = (const float*)d_in[12];
    float* out = (float*)d_out;

    const dim3 gGemm(M_ALL / 128, FOURH / 64);   // (512, 32)
    const int zBlocks = (B_ * H_ + 255) / 256;

    // layer 0
    zero_state_kernel<<<zBlocks, 256>>>();
    gemm_xw_kernel<<<gGemm, 256>>>(x, 0, Wih0, b0, D_);
    for (int t = 0; t < T_; t++)
        lstm_step_kernel<<<GRID_S, 256>>>(Whh0, t, 0);

    // layer 1
    zero_state_kernel<<<zBlocks, 256>>>();
    gemm_xw_kernel<<<gGemm, 256>>>(nullptr, 1, Wih1, b1, H_);
    for (int t = 0; t < T_; t++)
        lstm_step_kernel<<<GRID_S, 256>>>(Whh1, t, 1);

    // heads
    head1_kernel<<<B_, 256>>>(Wsh, bsh);
    head2_kernel<<<1, 256>>>(Wdir, bdir, Wmag, bmag, out);
}